// round 3
// baseline (speedup 1.0000x reference)
#include <cuda_runtime.h>

#define T_TOK 500000
#define M_MEN 50000
#define B_BAG 5000
#define V_VOC 100000
#define D_DIM 256
#define K_TYP 100

// Scratch (no allocations allowed)
__device__ float g_men_emb[M_MEN * D_DIM];      // 51.2 MB
__device__ float g_sel[M_MEN];
__device__ float g_bag_emb[B_BAG * D_DIM];      // 5.12 MB
__device__ int   g_type_idx[B_BAG];

// ---------------------------------------------------------------------------
// K0: per-bag argmax over typeTensor[b, 0:100]  (one warp per bag)
// ---------------------------------------------------------------------------
__global__ void k0_argmax(const float* __restrict__ typeT, int* __restrict__ tidx) {
    int b    = blockIdx.x * (blockDim.x >> 5) + (threadIdx.x >> 5);
    int lane = threadIdx.x & 31;
    if (b >= B_BAG) return;
    float best = -INFINITY; int bi = K_TYP;
    for (int k = lane; k < K_TYP; k += 32) {
        float v = typeT[(size_t)b * K_TYP + k];
        if (v > best) { best = v; bi = k; }
    }
    #pragma unroll
    for (int off = 16; off; off >>= 1) {
        float ov = __shfl_xor_sync(0xffffffffu, best, off);
        int   oi = __shfl_xor_sync(0xffffffffu, bi,   off);
        if (ov > best || (ov == best && oi < bi)) { best = ov; bi = oi; }
    }
    if (lane == 0) tidx[b] = bi;
}

// ---------------------------------------------------------------------------
// K1: one warp per mention. Gather+mean token embeddings -> men_emb[m],
//     fused dot with linear_weight[type_idx[bag(m)]] -> sel[m].
//     4-token unroll: 8 independent 128B loads in flight per lane.
// ---------------------------------------------------------------------------
__global__ void k1_mention(const int*   __restrict__ feat,
                           const int*   __restrict__ offs,
                           const int*   __restrict__ scope,
                           const float* __restrict__ emb,
                           const float* __restrict__ lw,
                           const int*   __restrict__ tidx_arr) {
    int m    = blockIdx.x * (blockDim.x >> 5) + (threadIdx.x >> 5);
    int lane = threadIdx.x & 31;
    if (m >= M_MEN) return;

    int start = offs[m];
    int end   = (m + 1 < M_MEN) ? offs[m + 1] : T_TOK;

    // bag id: largest b with scope[b] <= m
    int lo = 0, hi = B_BAG;
    while (hi - lo > 1) {
        int mid = (lo + hi) >> 1;
        if (scope[mid] <= m) lo = mid; else hi = mid;
    }
    int t = tidx_arr[lo];

    float4 a0 = make_float4(0.f, 0.f, 0.f, 0.f);
    float4 a1 = make_float4(0.f, 0.f, 0.f, 0.f);

    int p = start;
    for (; p + 4 <= end; p += 4) {
        int tA = feat[p], tB = feat[p + 1], tC = feat[p + 2], tD = feat[p + 3];
        const float4* rA = (const float4*)(emb + (size_t)tA * D_DIM);
        const float4* rB = (const float4*)(emb + (size_t)tB * D_DIM);
        const float4* rC = (const float4*)(emb + (size_t)tC * D_DIM);
        const float4* rD = (const float4*)(emb + (size_t)tD * D_DIM);
        float4 vA0 = rA[lane], vA1 = rA[lane + 32];
        float4 vB0 = rB[lane], vB1 = rB[lane + 32];
        float4 vC0 = rC[lane], vC1 = rC[lane + 32];
        float4 vD0 = rD[lane], vD1 = rD[lane + 32];
        a0.x += (vA0.x + vB0.x) + (vC0.x + vD0.x);
        a0.y += (vA0.y + vB0.y) + (vC0.y + vD0.y);
        a0.z += (vA0.z + vB0.z) + (vC0.z + vD0.z);
        a0.w += (vA0.w + vB0.w) + (vC0.w + vD0.w);
        a1.x += (vA1.x + vB1.x) + (vC1.x + vD1.x);
        a1.y += (vA1.y + vB1.y) + (vC1.y + vD1.y);
        a1.z += (vA1.z + vB1.z) + (vC1.z + vD1.z);
        a1.w += (vA1.w + vB1.w) + (vC1.w + vD1.w);
    }
    for (; p < end; p++) {
        int tok = feat[p];
        const float4* row = (const float4*)(emb + (size_t)tok * D_DIM);
        float4 v0 = row[lane], v1 = row[lane + 32];
        a0.x += v0.x; a0.y += v0.y; a0.z += v0.z; a0.w += v0.w;
        a1.x += v1.x; a1.y += v1.y; a1.z += v1.z; a1.w += v1.w;
    }
    float inv = 1.0f / (float)(end - start);
    a0.x *= inv; a0.y *= inv; a0.z *= inv; a0.w *= inv;
    a1.x *= inv; a1.y *= inv; a1.z *= inv; a1.w *= inv;

    // evict-first stores: men_emb is read exactly once (by k3a); keep emb in L2
    float4* mrow = (float4*)(g_men_emb + (size_t)m * D_DIM);
    __stcs(&mrow[lane],      a0);
    __stcs(&mrow[lane + 32], a1);

    const float4* w = (const float4*)(lw + (size_t)t * D_DIM);
    float4 w0 = w[lane];
    float4 w1 = w[lane + 32];
    float d = a0.x * w0.x + a0.y * w0.y + a0.z * w0.z + a0.w * w0.w
            + a1.x * w1.x + a1.y * w1.y + a1.z * w1.z + a1.w * w1.w;
    #pragma unroll
    for (int off = 16; off; off >>= 1) d += __shfl_xor_sync(0xffffffffu, d, off);
    if (lane == 0) g_sel[m] = d;
}

// ---------------------------------------------------------------------------
// K3a: ONE WARP per bag. Softmax over sel + weighted sum of men_emb rows.
//      Lane covers 8 floats (2 float4) of the 256-wide row.
// ---------------------------------------------------------------------------
__global__ void k3a_bagemb(const int* __restrict__ scope,
                           float*     __restrict__ bag_emb) {
    int b    = blockIdx.x * (blockDim.x >> 5) + (threadIdx.x >> 5);
    int lane = threadIdx.x & 31;
    if (b >= B_BAG) return;
    int s = scope[b], e = scope[b + 1];

    float mx = -INFINITY;
    for (int m = s + lane; m < e; m += 32) mx = fmaxf(mx, g_sel[m]);
    #pragma unroll
    for (int off = 16; off; off >>= 1)
        mx = fmaxf(mx, __shfl_xor_sync(0xffffffffu, mx, off));

    float sum = 0.f;
    for (int m = s + lane; m < e; m += 32) sum += expf(g_sel[m] - mx);
    #pragma unroll
    for (int off = 16; off; off >>= 1)
        sum += __shfl_xor_sync(0xffffffffu, sum, off);
    float inv = 1.0f / sum;

    float4 a0 = make_float4(0.f, 0.f, 0.f, 0.f);
    float4 a1 = make_float4(0.f, 0.f, 0.f, 0.f);
    int m = s;
    for (; m + 2 <= e; m += 2) {
        float wA = expf(g_sel[m]     - mx);
        float wB = expf(g_sel[m + 1] - mx);
        const float4* rA = (const float4*)(g_men_emb + (size_t)m       * D_DIM);
        const float4* rB = (const float4*)(g_men_emb + (size_t)(m + 1) * D_DIM);
        float4 vA0 = __ldcs(&rA[lane]);
        float4 vA1 = __ldcs(&rA[lane + 32]);
        float4 vB0 = __ldcs(&rB[lane]);
        float4 vB1 = __ldcs(&rB[lane + 32]);
        a0.x += wA * vA0.x + wB * vB0.x;  a0.y += wA * vA0.y + wB * vB0.y;
        a0.z += wA * vA0.z + wB * vB0.z;  a0.w += wA * vA0.w + wB * vB0.w;
        a1.x += wA * vA1.x + wB * vB1.x;  a1.y += wA * vA1.y + wB * vB1.y;
        a1.z += wA * vA1.z + wB * vB1.z;  a1.w += wA * vA1.w + wB * vB1.w;
    }
    for (; m < e; m++) {
        float w = expf(g_sel[m] - mx);
        const float4* r = (const float4*)(g_men_emb + (size_t)m * D_DIM);
        float4 v0 = __ldcs(&r[lane]);
        float4 v1 = __ldcs(&r[lane + 32]);
        a0.x += w * v0.x; a0.y += w * v0.y; a0.z += w * v0.z; a0.w += w * v0.w;
        a1.x += w * v1.x; a1.y += w * v1.y; a1.z += w * v1.z; a1.w += w * v1.w;
    }
    a0.x *= inv; a0.y *= inv; a0.z *= inv; a0.w *= inv;
    a1.x *= inv; a1.y *= inv; a1.z *= inv; a1.w *= inv;

    float4* brow = (float4*)(bag_emb + (size_t)b * D_DIM);
    brow[lane]      = a0;
    brow[lane + 32] = a1;
}

// ---------------------------------------------------------------------------
// K3b: register-tiled GEMM  out[5000,100] = bag_emb[5000,256] @ W[100,256]^T
//      128 threads, tile 16 bags x 128 k -> grid=313 (better latency hiding).
//      kt=tid&31 owns 4 k's; bt=tid>>5 owns 4 bags. a-loads are warp-broadcast.
// ---------------------------------------------------------------------------
#define GEMM_BM 16
__global__ void k3b_gemm(const float* __restrict__ A,
                         const float* __restrict__ W,
                         float*       __restrict__ out) {
    __shared__ float sA[32][17];    // [d][bag]
    __shared__ float sW[128][33];   // [k][d]
    int tid = threadIdx.x;          // 128 threads
    int kt = tid & 31;
    int bt = tid >> 5;              // 0..3, each owns 4 bags
    int bag0 = blockIdx.x * GEMM_BM;

    float acc[4][4];
    #pragma unroll
    for (int r = 0; r < 4; r++)
        #pragma unroll
        for (int j = 0; j < 4; j++) acc[r][j] = 0.f;

    for (int d0 = 0; d0 < D_DIM; d0 += 32) {
        // A tile: 16 bags x 32 d = 128 float4, 1 per thread
        {
            int b = tid >> 3, x = tid & 7;
            int bag = bag0 + b;
            float4 v = (bag < B_BAG)
                ? *(const float4*)(A + (size_t)bag * D_DIM + d0 + 4 * x)
                : make_float4(0.f, 0.f, 0.f, 0.f);
            sA[4 * x + 0][b] = v.x; sA[4 * x + 1][b] = v.y;
            sA[4 * x + 2][b] = v.z; sA[4 * x + 3][b] = v.w;
        }
        // W tile: 128 k x 32 d = 1024 float4, 8 per thread
        #pragma unroll
        for (int i = 0; i < 8; i++) {
            int idx = tid + 128 * i;
            int k = idx >> 3, x = idx & 7;
            float4 v = (k < K_TYP)
                ? *(const float4*)(W + (size_t)k * D_DIM + d0 + 4 * x)
                : make_float4(0.f, 0.f, 0.f, 0.f);
            sW[k][4 * x + 0] = v.x; sW[k][4 * x + 1] = v.y;
            sW[k][4 * x + 2] = v.z; sW[k][4 * x + 3] = v.w;
        }
        __syncthreads();

        #pragma unroll
        for (int d = 0; d < 32; d++) {
            float a0 = sA[d][bt * 4 + 0];
            float a1 = sA[d][bt * 4 + 1];
            float a2 = sA[d][bt * 4 + 2];
            float a3 = sA[d][bt * 4 + 3];
            float w0 = sW[kt      ][d];
            float w1 = sW[kt + 32 ][d];
            float w2 = sW[kt + 64 ][d];
            float w3 = sW[kt + 96 ][d];
            acc[0][0] += a0 * w0; acc[0][1] += a0 * w1; acc[0][2] += a0 * w2; acc[0][3] += a0 * w3;
            acc[1][0] += a1 * w0; acc[1][1] += a1 * w1; acc[1][2] += a1 * w2; acc[1][3] += a1 * w3;
            acc[2][0] += a2 * w0; acc[2][1] += a2 * w1; acc[2][2] += a2 * w2; acc[2][3] += a2 * w3;
            acc[3][0] += a3 * w0; acc[3][1] += a3 * w1; acc[3][2] += a3 * w2; acc[3][3] += a3 * w3;
        }
        __syncthreads();
    }

    #pragma unroll
    for (int r = 0; r < 4; r++) {
        int bag = bag0 + bt * 4 + r;
        if (bag >= B_BAG) continue;
        #pragma unroll
        for (int j = 0; j < 4; j++) {
            int k = kt + 32 * j;
            if (k < K_TYP) out[(size_t)bag * K_TYP + k] = acc[r][j];
        }
    }
}

// ---------------------------------------------------------------------------
extern "C" void kernel_launch(void* const* d_in, const int* in_sizes, int n_in,
                              void* d_out, int out_size) {
    const int*   feature_seq    = (const int*)  d_in[0];
    const int*   offset_seq     = (const int*)  d_in[1];
    const int*   scope          = (const int*)  d_in[2];
    const float* typeTensor     = (const float*)d_in[3];
    const float* word_embedding = (const float*)d_in[4];
    const float* linear_weight  = (const float*)d_in[5];
    float*       out            = (float*)d_out;

    int*   tidx = nullptr;
    float* bagE = nullptr;
    cudaGetSymbolAddress((void**)&tidx, g_type_idx);
    cudaGetSymbolAddress((void**)&bagE, g_bag_emb);

    k0_argmax<<<(B_BAG + 7) / 8, 256>>>(typeTensor, tidx);
    k1_mention<<<(M_MEN + 7) / 8, 256>>>(feature_seq, offset_seq, scope,
                                         word_embedding, linear_weight, tidx);
    k3a_bagemb<<<(B_BAG + 7) / 8, 256>>>(scope, bagE);
    k3b_gemm<<<(B_BAG + GEMM_BM - 1) / GEMM_BM, 128>>>(bagE, linear_weight, out);
}

// round 4
// speedup vs baseline: 1.0872x; 1.0872x over previous
#include <cuda_runtime.h>

#define T_TOK 500000
#define M_MEN 50000
#define B_BAG 5000
#define V_VOC 100000
#define D_DIM 256
#define K_TYP 100
#define K_PAD 128

// Scratch (no allocations allowed)
__device__ float g_men_emb[M_MEN * D_DIM];      // 51.2 MB
__device__ float g_sel[M_MEN];
__device__ float g_bag_emb[B_BAG * D_DIM];      // 5.12 MB
__device__ float g_Wt[D_DIM * K_PAD];           // 128 KB, W transposed d-major
__device__ int   g_type_idx[B_BAG];

// ---------------------------------------------------------------------------
// K0: per-bag argmax over typeTensor[b, 0:100]  (one warp per bag)
// ---------------------------------------------------------------------------
__global__ void k0_argmax(const float* __restrict__ typeT, int* __restrict__ tidx) {
    int b    = blockIdx.x * (blockDim.x >> 5) + (threadIdx.x >> 5);
    int lane = threadIdx.x & 31;
    if (b >= B_BAG) return;
    float best = -INFINITY; int bi = K_TYP;
    for (int k = lane; k < K_TYP; k += 32) {
        float v = typeT[(size_t)b * K_TYP + k];
        if (v > best) { best = v; bi = k; }
    }
    #pragma unroll
    for (int off = 16; off; off >>= 1) {
        float ov = __shfl_xor_sync(0xffffffffu, best, off);
        int   oi = __shfl_xor_sync(0xffffffffu, bi,   off);
        if (ov > best || (ov == best && oi < bi)) { best = ov; bi = oi; }
    }
    if (lane == 0) tidx[b] = bi;
}

// ---------------------------------------------------------------------------
// K0b: transpose W[100,256] -> g_Wt[256,128] (d-major, zero-padded k)
// ---------------------------------------------------------------------------
__global__ void k0b_transpose(const float* __restrict__ W, float* __restrict__ Wt) {
    int idx = blockIdx.x * blockDim.x + threadIdx.x;   // over 256*128
    if (idx >= D_DIM * K_PAD) return;
    int d = idx >> 7, k = idx & 127;
    Wt[idx] = (k < K_TYP) ? W[(size_t)k * D_DIM + d] : 0.f;
}

// ---------------------------------------------------------------------------
// K1: one warp per mention. Gather+mean token embeddings -> men_emb[m],
//     fused dot with linear_weight[type_idx[bag(m)]] -> sel[m].
//     (round-2 form: 2-token unroll — best measured)
// ---------------------------------------------------------------------------
__global__ void k1_mention(const int*   __restrict__ feat,
                           const int*   __restrict__ offs,
                           const int*   __restrict__ scope,
                           const float* __restrict__ emb,
                           const float* __restrict__ lw,
                           const int*   __restrict__ tidx_arr) {
    int m    = blockIdx.x * (blockDim.x >> 5) + (threadIdx.x >> 5);
    int lane = threadIdx.x & 31;
    if (m >= M_MEN) return;

    int start = offs[m];
    int end   = (m + 1 < M_MEN) ? offs[m + 1] : T_TOK;

    int lo = 0, hi = B_BAG;
    while (hi - lo > 1) {
        int mid = (lo + hi) >> 1;
        if (scope[mid] <= m) lo = mid; else hi = mid;
    }
    int t = tidx_arr[lo];

    float4 a0 = make_float4(0.f, 0.f, 0.f, 0.f);
    float4 a1 = make_float4(0.f, 0.f, 0.f, 0.f);

    int p = start;
    for (; p + 2 <= end; p += 2) {
        int tokA = feat[p], tokB = feat[p + 1];
        const float4* rA = (const float4*)(emb + (size_t)tokA * D_DIM);
        const float4* rB = (const float4*)(emb + (size_t)tokB * D_DIM);
        float4 vA0 = rA[lane], vA1 = rA[lane + 32];
        float4 vB0 = rB[lane], vB1 = rB[lane + 32];
        a0.x += vA0.x + vB0.x; a0.y += vA0.y + vB0.y;
        a0.z += vA0.z + vB0.z; a0.w += vA0.w + vB0.w;
        a1.x += vA1.x + vB1.x; a1.y += vA1.y + vB1.y;
        a1.z += vA1.z + vB1.z; a1.w += vA1.w + vB1.w;
    }
    for (; p < end; p++) {
        int tok = feat[p];
        const float4* row = (const float4*)(emb + (size_t)tok * D_DIM);
        float4 v0 = row[lane], v1 = row[lane + 32];
        a0.x += v0.x; a0.y += v0.y; a0.z += v0.z; a0.w += v0.w;
        a1.x += v1.x; a1.y += v1.y; a1.z += v1.z; a1.w += v1.w;
    }
    float inv = 1.0f / (float)(end - start);
    a0.x *= inv; a0.y *= inv; a0.z *= inv; a0.w *= inv;
    a1.x *= inv; a1.y *= inv; a1.z *= inv; a1.w *= inv;

    float4* mrow = (float4*)(g_men_emb + (size_t)m * D_DIM);
    __stcs(&mrow[lane],      a0);
    __stcs(&mrow[lane + 32], a1);

    const float4* w = (const float4*)(lw + (size_t)t * D_DIM);
    float4 w0 = w[lane];
    float4 w1 = w[lane + 32];
    float d = a0.x * w0.x + a0.y * w0.y + a0.z * w0.z + a0.w * w0.w
            + a1.x * w1.x + a1.y * w1.y + a1.z * w1.z + a1.w * w1.w;
    #pragma unroll
    for (int off = 16; off; off >>= 1) d += __shfl_xor_sync(0xffffffffu, d, off);
    if (lane == 0) g_sel[m] = d;
}

// ---------------------------------------------------------------------------
// K3a: ONE WARP per bag. Softmax over sel + weighted sum of men_emb rows.
// ---------------------------------------------------------------------------
__global__ void k3a_bagemb(const int* __restrict__ scope,
                           float*     __restrict__ bag_emb) {
    int b    = blockIdx.x * (blockDim.x >> 5) + (threadIdx.x >> 5);
    int lane = threadIdx.x & 31;
    if (b >= B_BAG) return;
    int s = scope[b], e = scope[b + 1];

    float mx = -INFINITY;
    for (int m = s + lane; m < e; m += 32) mx = fmaxf(mx, g_sel[m]);
    #pragma unroll
    for (int off = 16; off; off >>= 1)
        mx = fmaxf(mx, __shfl_xor_sync(0xffffffffu, mx, off));

    float sum = 0.f;
    for (int m = s + lane; m < e; m += 32) sum += expf(g_sel[m] - mx);
    #pragma unroll
    for (int off = 16; off; off >>= 1)
        sum += __shfl_xor_sync(0xffffffffu, sum, off);
    float inv = 1.0f / sum;

    float4 a0 = make_float4(0.f, 0.f, 0.f, 0.f);
    float4 a1 = make_float4(0.f, 0.f, 0.f, 0.f);
    int m = s;
    for (; m + 2 <= e; m += 2) {
        float wA = expf(g_sel[m]     - mx);
        float wB = expf(g_sel[m + 1] - mx);
        const float4* rA = (const float4*)(g_men_emb + (size_t)m       * D_DIM);
        const float4* rB = (const float4*)(g_men_emb + (size_t)(m + 1) * D_DIM);
        float4 vA0 = __ldcs(&rA[lane]);
        float4 vA1 = __ldcs(&rA[lane + 32]);
        float4 vB0 = __ldcs(&rB[lane]);
        float4 vB1 = __ldcs(&rB[lane + 32]);
        a0.x += wA * vA0.x + wB * vB0.x;  a0.y += wA * vA0.y + wB * vB0.y;
        a0.z += wA * vA0.z + wB * vB0.z;  a0.w += wA * vA0.w + wB * vB0.w;
        a1.x += wA * vA1.x + wB * vB1.x;  a1.y += wA * vA1.y + wB * vB1.y;
        a1.z += wA * vA1.z + wB * vB1.z;  a1.w += wA * vA1.w + wB * vB1.w;
    }
    for (; m < e; m++) {
        float w = expf(g_sel[m] - mx);
        const float4* r = (const float4*)(g_men_emb + (size_t)m * D_DIM);
        float4 v0 = __ldcs(&r[lane]);
        float4 v1 = __ldcs(&r[lane + 32]);
        a0.x += w * v0.x; a0.y += w * v0.y; a0.z += w * v0.z; a0.w += w * v0.w;
        a1.x += w * v1.x; a1.y += w * v1.y; a1.z += w * v1.z; a1.w += w * v1.w;
    }
    a0.x *= inv; a0.y *= inv; a0.z *= inv; a0.w *= inv;
    a1.x *= inv; a1.y *= inv; a1.z *= inv; a1.w *= inv;

    float4* brow = (float4*)(bag_emb + (size_t)b * D_DIM);
    brow[lane]      = a0;
    brow[lane + 32] = a1;
}

// ---------------------------------------------------------------------------
// K3b: GEMM out[5000,100] = bag_emb @ W^T using d-major g_Wt.
//      128 threads, tile 16 bags x 128 k. Per d-step:
//        1x LDS.128 (Wt row slice, conflict-free) +
//        1x LDS.128 broadcast (A bags) + 16 FMA  -> 1:8 load:FMA.
//      kt = tid&31 owns k = 4*kt..4*kt+3 (vector); bt = tid>>5 owns 4 bags.
// ---------------------------------------------------------------------------
#define GEMM_BM 16
#define DSTAGE  64
__global__ void k3b_gemm(const float* __restrict__ A,
                         const float* __restrict__ Wt,
                         float*       __restrict__ out) {
    __shared__ float sW[DSTAGE][K_PAD];       // [d][k], rows 512B
    __shared__ float sA[DSTAGE][GEMM_BM + 4]; // [d][bag]
    int tid = threadIdx.x;                    // 128 threads
    int kt = tid & 31;                        // k group: 4*kt
    int bt = tid >> 5;                        // bag group: 4*bt
    int bag0 = blockIdx.x * GEMM_BM;

    float4 acc[4];                            // acc[r] = k-vector for bag r
    #pragma unroll
    for (int r = 0; r < 4; r++) acc[r] = make_float4(0.f, 0.f, 0.f, 0.f);

    for (int d0 = 0; d0 < D_DIM; d0 += DSTAGE) {
        // Load Wt tile: 64 d x 128 k = 2048 float4, 16 per thread, coalesced.
        #pragma unroll
        for (int i = 0; i < 16; i++) {
            int idx = tid + 128 * i;              // float4 index in tile
            int d = idx >> 5, x = idx & 31;       // 32 float4 per row
            *(float4*)&sW[d][4 * x] =
                *(const float4*)(Wt + (size_t)(d0 + d) * K_PAD + 4 * x);
        }
        // Load A tile: 16 bags x 64 d = 256 float4, 2 per thread, transpose-store.
        #pragma unroll
        for (int i = 0; i < 2; i++) {
            int idx = tid + 128 * i;
            int b = idx >> 4, x = idx & 15;       // 16 float4 per bag row
            int bag = bag0 + b;
            float4 v = (bag < B_BAG)
                ? *(const float4*)(A + (size_t)bag * D_DIM + d0 + 4 * x)
                : make_float4(0.f, 0.f, 0.f, 0.f);
            sA[4 * x + 0][b] = v.x; sA[4 * x + 1][b] = v.y;
            sA[4 * x + 2][b] = v.z; sA[4 * x + 3][b] = v.w;
        }
        __syncthreads();

        #pragma unroll 16
        for (int d = 0; d < DSTAGE; d++) {
            float4 wv = *(const float4*)&sW[d][4 * kt];
            float4 av = *(const float4*)&sA[d][4 * bt];   // warp-broadcast
            acc[0].x += av.x * wv.x; acc[0].y += av.x * wv.y;
            acc[0].z += av.x * wv.z; acc[0].w += av.x * wv.w;
            acc[1].x += av.y * wv.x; acc[1].y += av.y * wv.y;
            acc[1].z += av.y * wv.z; acc[1].w += av.y * wv.w;
            acc[2].x += av.z * wv.x; acc[2].y += av.z * wv.y;
            acc[2].z += av.z * wv.z; acc[2].w += av.z * wv.w;
            acc[3].x += av.w * wv.x; acc[3].y += av.w * wv.y;
            acc[3].z += av.w * wv.z; acc[3].w += av.w * wv.w;
        }
        __syncthreads();
    }

    // Store: k = 4*kt..4*kt+3 (contiguous). K_TYP=100: kt<25 fully inside.
    #pragma unroll
    for (int r = 0; r < 4; r++) {
        int bag = bag0 + 4 * bt + r;
        if (bag >= B_BAG) continue;
        int k = 4 * kt;
        if (k + 4 <= K_TYP) {
            *(float4*)(out + (size_t)bag * K_TYP + k) = acc[r];
        } else if (k < K_TYP) {
            float v[4] = {acc[r].x, acc[r].y, acc[r].z, acc[r].w};
            for (int j = 0; j < 4 && k + j < K_TYP; j++)
                out[(size_t)bag * K_TYP + k + j] = v[j];
        }
    }
}

// ---------------------------------------------------------------------------
extern "C" void kernel_launch(void* const* d_in, const int* in_sizes, int n_in,
                              void* d_out, int out_size) {
    const int*   feature_seq    = (const int*)  d_in[0];
    const int*   offset_seq     = (const int*)  d_in[1];
    const int*   scope          = (const int*)  d_in[2];
    const float* typeTensor     = (const float*)d_in[3];
    const float* word_embedding = (const float*)d_in[4];
    const float* linear_weight  = (const float*)d_in[5];
    float*       out            = (float*)d_out;

    int*   tidx = nullptr;
    float* bagE = nullptr;
    float* Wt   = nullptr;
    cudaGetSymbolAddress((void**)&tidx, g_type_idx);
    cudaGetSymbolAddress((void**)&bagE, g_bag_emb);
    cudaGetSymbolAddress((void**)&Wt,   g_Wt);

    k0_argmax<<<(B_BAG + 7) / 8, 256>>>(typeTensor, tidx);
    k0b_transpose<<<(D_DIM * K_PAD + 255) / 256, 256>>>(linear_weight, Wt);
    k1_mention<<<(M_MEN + 7) / 8, 256>>>(feature_seq, offset_seq, scope,
                                         word_embedding, linear_weight, tidx);
    k3a_bagemb<<<(B_BAG + 7) / 8, 256>>>(scope, bagE);
    k3b_gemm<<<(B_BAG + GEMM_BM - 1) / GEMM_BM, 128>>>(bagE, Wt, out);
}

// round 5
// speedup vs baseline: 1.2473x; 1.1473x over previous
#include <cuda_runtime.h>

#define T_TOK 500000
#define M_MEN 50000
#define B_BAG 5000
#define V_VOC 100000
#define D_DIM 256
#define K_TYP 100
#define K_PAD 128

// Scratch (no allocations allowed)
__device__ float g_men_emb[M_MEN * D_DIM];      // 51.2 MB
__device__ float g_sel[M_MEN];
__device__ float g_bag_emb[B_BAG * D_DIM];      // 5.12 MB
__device__ float g_Wt[D_DIM * K_PAD];           // 128 KB, W transposed d-major
__device__ int   g_type_idx[B_BAG];
__device__ int   g_men_type[M_MEN];             // per-mention selected type

// ---------------------------------------------------------------------------
// K0: per-bag argmax over typeTensor + scatter type to the bag's mentions.
// ---------------------------------------------------------------------------
__global__ void k0_argmax(const float* __restrict__ typeT,
                          const int*   __restrict__ scope,
                          int* __restrict__ tidx,
                          int* __restrict__ men_type) {
    int b    = blockIdx.x * (blockDim.x >> 5) + (threadIdx.x >> 5);
    int lane = threadIdx.x & 31;
    if (b >= B_BAG) return;
    float best = -INFINITY; int bi = K_TYP;
    for (int k = lane; k < K_TYP; k += 32) {
        float v = typeT[(size_t)b * K_TYP + k];
        if (v > best) { best = v; bi = k; }
    }
    #pragma unroll
    for (int off = 16; off; off >>= 1) {
        float ov = __shfl_xor_sync(0xffffffffu, best, off);
        int   oi = __shfl_xor_sync(0xffffffffu, bi,   off);
        if (ov > best || (ov == best && oi < bi)) { best = ov; bi = oi; }
    }
    if (lane == 0) tidx[b] = bi;
    // butterfly leaves the final bi in every lane: scatter to mention range
    int s = scope[b], e = scope[b + 1];
    for (int j = s + lane; j < e; j += 32) men_type[j] = bi;
}

// ---------------------------------------------------------------------------
// K0b: transpose W[100,256] -> g_Wt[256,128] (d-major, zero-padded k)
// ---------------------------------------------------------------------------
__global__ void k0b_transpose(const float* __restrict__ W, float* __restrict__ Wt) {
    int idx = blockIdx.x * blockDim.x + threadIdx.x;
    if (idx >= D_DIM * K_PAD) return;
    int d = idx >> 7, k = idx & 127;
    Wt[idx] = (k < K_TYP) ? W[(size_t)k * D_DIM + d] : 0.f;
}

// ---------------------------------------------------------------------------
// K1: TWO warps per mention (each owns 128 dims = 1 float4 per lane).
//     4-token unroll -> 4 independent 128B loads in flight per warp.
//     Gather+mean -> men_emb; fused dot with W[men_type[m]] -> sel[m]
//     (warp-pair partials combined via smem).
//     Grid: 12500 blocks x 256 thr = 100000 warps = 2*M exactly.
// ---------------------------------------------------------------------------
__global__ void k1_mention(const int*   __restrict__ feat,
                           const int*   __restrict__ offs,
                           const float* __restrict__ emb,
                           const float* __restrict__ lw,
                           const int*   __restrict__ men_type) {
    int wid  = threadIdx.x >> 5;               // 0..7
    int lane = threadIdx.x & 31;
    int gw   = blockIdx.x * 8 + wid;           // global warp
    int m    = gw >> 1;
    int half = gw & 1;                         // which 128-dim half

    int start = offs[m];
    int end   = (m + 1 < M_MEN) ? offs[m + 1] : T_TOK;

    // float4 column this warp/lane owns
    int col4 = half * 32 + lane;               // float4 index within row (0..63)

    float4 acc = make_float4(0.f, 0.f, 0.f, 0.f);
    int p = start;
    for (; p + 4 <= end; p += 4) {
        int t0 = feat[p],     t1 = feat[p + 1];
        int t2 = feat[p + 2], t3 = feat[p + 3];
        float4 v0 = ((const float4*)(emb + (size_t)t0 * D_DIM))[col4];
        float4 v1 = ((const float4*)(emb + (size_t)t1 * D_DIM))[col4];
        float4 v2 = ((const float4*)(emb + (size_t)t2 * D_DIM))[col4];
        float4 v3 = ((const float4*)(emb + (size_t)t3 * D_DIM))[col4];
        acc.x += (v0.x + v1.x) + (v2.x + v3.x);
        acc.y += (v0.y + v1.y) + (v2.y + v3.y);
        acc.z += (v0.z + v1.z) + (v2.z + v3.z);
        acc.w += (v0.w + v1.w) + (v2.w + v3.w);
    }
    for (; p < end; p++) {
        int t0 = feat[p];
        float4 v0 = ((const float4*)(emb + (size_t)t0 * D_DIM))[col4];
        acc.x += v0.x; acc.y += v0.y; acc.z += v0.z; acc.w += v0.w;
    }
    float inv = 1.0f / (float)(end - start);
    acc.x *= inv; acc.y *= inv; acc.z *= inv; acc.w *= inv;

    // evict-first store (men_emb read exactly once by k3a)
    __stcs(&((float4*)(g_men_emb + (size_t)m * D_DIM))[col4], acc);

    // partial dot with selected type row
    int t = men_type[m];
    float4 w = ((const float4*)(lw + (size_t)t * D_DIM))[col4];
    float d = acc.x * w.x + acc.y * w.y + acc.z * w.z + acc.w * w.w;
    #pragma unroll
    for (int off = 16; off; off >>= 1) d += __shfl_xor_sync(0xffffffffu, d, off);

    __shared__ float part[8];
    if (lane == 0) part[wid] = d;
    __syncthreads();
    if ((wid & 1) == 0 && lane == 0)
        g_sel[m] = part[wid] + part[wid + 1];
}

// ---------------------------------------------------------------------------
// K3a: one 256-thread block per bag. Warp 0 computes mx/sum; att weights
//      computed ONCE per mention into smem; main loop 8-deep unrolled __ldcs.
// ---------------------------------------------------------------------------
#define ATT_CHUNK 128
__global__ void k3a_bagemb(const int* __restrict__ scope,
                           float*     __restrict__ bag_emb) {
    int b   = blockIdx.x;
    int tid = threadIdx.x, lane = tid & 31, warp = tid >> 5;
    int s = scope[b], e = scope[b + 1];

    __shared__ float s_mx, s_inv;
    __shared__ float att_s[ATT_CHUNK];

    if (warp == 0) {
        float mx = -INFINITY;
        for (int m = s + lane; m < e; m += 32) mx = fmaxf(mx, g_sel[m]);
        #pragma unroll
        for (int off = 16; off; off >>= 1)
            mx = fmaxf(mx, __shfl_xor_sync(0xffffffffu, mx, off));
        float sum = 0.f;
        for (int m = s + lane; m < e; m += 32) sum += expf(g_sel[m] - mx);
        #pragma unroll
        for (int off = 16; off; off >>= 1)
            sum += __shfl_xor_sync(0xffffffffu, sum, off);
        if (lane == 0) { s_mx = mx; s_inv = 1.0f / sum; }
    }
    __syncthreads();
    float mx = s_mx, inv = s_inv;

    float acc = 0.f;
    for (int c0 = s; c0 < e; c0 += ATT_CHUNK) {
        int n = min(ATT_CHUNK, e - c0);
        if (tid < n) att_s[tid] = expf(g_sel[c0 + tid] - mx) * inv;
        __syncthreads();

        const float* base = g_men_emb + (size_t)c0 * D_DIM + tid;
        int i = 0;
        for (; i + 8 <= n; i += 8) {
            float v0 = __ldcs(base + (size_t)(i + 0) * D_DIM);
            float v1 = __ldcs(base + (size_t)(i + 1) * D_DIM);
            float v2 = __ldcs(base + (size_t)(i + 2) * D_DIM);
            float v3 = __ldcs(base + (size_t)(i + 3) * D_DIM);
            float v4 = __ldcs(base + (size_t)(i + 4) * D_DIM);
            float v5 = __ldcs(base + (size_t)(i + 5) * D_DIM);
            float v6 = __ldcs(base + (size_t)(i + 6) * D_DIM);
            float v7 = __ldcs(base + (size_t)(i + 7) * D_DIM);
            acc += att_s[i + 0] * v0 + att_s[i + 1] * v1
                 + att_s[i + 2] * v2 + att_s[i + 3] * v3
                 + att_s[i + 4] * v4 + att_s[i + 5] * v5
                 + att_s[i + 6] * v6 + att_s[i + 7] * v7;
        }
        for (; i < n; i++)
            acc += att_s[i] * __ldcs(base + (size_t)i * D_DIM);
        __syncthreads();
    }

    bag_emb[(size_t)b * D_DIM + tid] = acc;
}

// ---------------------------------------------------------------------------
// K3b: GEMM out[5000,100] = bag_emb @ W^T using d-major g_Wt.
// ---------------------------------------------------------------------------
#define GEMM_BM 16
#define DSTAGE  64
__global__ void k3b_gemm(const float* __restrict__ A,
                         const float* __restrict__ Wt,
                         float*       __restrict__ out) {
    __shared__ float sW[DSTAGE][K_PAD];
    __shared__ float sA[DSTAGE][GEMM_BM + 4];
    int tid = threadIdx.x;                    // 128 threads
    int kt = tid & 31;
    int bt = tid >> 5;
    int bag0 = blockIdx.x * GEMM_BM;

    float4 acc[4];
    #pragma unroll
    for (int r = 0; r < 4; r++) acc[r] = make_float4(0.f, 0.f, 0.f, 0.f);

    for (int d0 = 0; d0 < D_DIM; d0 += DSTAGE) {
        #pragma unroll
        for (int i = 0; i < 16; i++) {
            int idx = tid + 128 * i;
            int d = idx >> 5, x = idx & 31;
            *(float4*)&sW[d][4 * x] =
                *(const float4*)(Wt + (size_t)(d0 + d) * K_PAD + 4 * x);
        }
        #pragma unroll
        for (int i = 0; i < 2; i++) {
            int idx = tid + 128 * i;
            int b = idx >> 4, x = idx & 15;
            int bag = bag0 + b;
            float4 v = (bag < B_BAG)
                ? *(const float4*)(A + (size_t)bag * D_DIM + d0 + 4 * x)
                : make_float4(0.f, 0.f, 0.f, 0.f);
            sA[4 * x + 0][b] = v.x; sA[4 * x + 1][b] = v.y;
            sA[4 * x + 2][b] = v.z; sA[4 * x + 3][b] = v.w;
        }
        __syncthreads();

        #pragma unroll 16
        for (int d = 0; d < DSTAGE; d++) {
            float4 wv = *(const float4*)&sW[d][4 * kt];
            float4 av = *(const float4*)&sA[d][4 * bt];
            acc[0].x += av.x * wv.x; acc[0].y += av.x * wv.y;
            acc[0].z += av.x * wv.z; acc[0].w += av.x * wv.w;
            acc[1].x += av.y * wv.x; acc[1].y += av.y * wv.y;
            acc[1].z += av.y * wv.z; acc[1].w += av.y * wv.w;
            acc[2].x += av.z * wv.x; acc[2].y += av.z * wv.y;
            acc[2].z += av.z * wv.z; acc[2].w += av.z * wv.w;
            acc[3].x += av.w * wv.x; acc[3].y += av.w * wv.y;
            acc[3].z += av.w * wv.z; acc[3].w += av.w * wv.w;
        }
        __syncthreads();
    }

    #pragma unroll
    for (int r = 0; r < 4; r++) {
        int bag = bag0 + 4 * bt + r;
        if (bag >= B_BAG) continue;
        int k = 4 * kt;
        if (k + 4 <= K_TYP) {
            *(float4*)(out + (size_t)bag * K_TYP + k) = acc[r];
        } else if (k < K_TYP) {
            float v[4] = {acc[r].x, acc[r].y, acc[r].z, acc[r].w};
            for (int j = 0; j < 4 && k + j < K_TYP; j++)
                out[(size_t)bag * K_TYP + k + j] = v[j];
        }
    }
}

// ---------------------------------------------------------------------------
extern "C" void kernel_launch(void* const* d_in, const int* in_sizes, int n_in,
                              void* d_out, int out_size) {
    const int*   feature_seq    = (const int*)  d_in[0];
    const int*   offset_seq     = (const int*)  d_in[1];
    const int*   scope          = (const int*)  d_in[2];
    const float* typeTensor     = (const float*)d_in[3];
    const float* word_embedding = (const float*)d_in[4];
    const float* linear_weight  = (const float*)d_in[5];
    float*       out            = (float*)d_out;

    int *tidx = nullptr, *mtype = nullptr;
    float *bagE = nullptr, *Wt = nullptr;
    cudaGetSymbolAddress((void**)&tidx,  g_type_idx);
    cudaGetSymbolAddress((void**)&mtype, g_men_type);
    cudaGetSymbolAddress((void**)&bagE,  g_bag_emb);
    cudaGetSymbolAddress((void**)&Wt,    g_Wt);

    k0_argmax<<<(B_BAG + 7) / 8, 256>>>(typeTensor, scope, tidx, mtype);
    k0b_transpose<<<(D_DIM * K_PAD + 255) / 256, 256>>>(linear_weight, Wt);
    k1_mention<<<(2 * M_MEN) / 8, 256>>>(feature_seq, offset_seq,
                                         word_embedding, linear_weight, mtype);
    k3a_bagemb<<<B_BAG, 256>>>(scope, bagE);
    k3b_gemm<<<(B_BAG + GEMM_BM - 1) / GEMM_BM, 128>>>(bagE, Wt, out);
}